// round 11
// baseline (speedup 1.0000x reference)
#include <cuda_runtime.h>
#include <cuda_bf16.h>
#include <math_constants.h>
#include <cstdint>

#define DIM     64
#define KCODE   1024
#define EPS_INT 140          // 140 * 2^-21 ~ 6.7e-5 ambiguity window
#define NPART   2048

// ---------------------------------------------------------------------------
// Device scratch (no cudaMalloc allowed)
__device__ float     g_wsum2[KCODE];    // exact sequential-chain ||w||^2
__device__ float     g_wsC21[KCODE];    // fl(fl(||w||^2 + 0.25) * 2^21)
__device__ double    g_part[NPART];
__device__ int       g_done;            // zero-init; self-resets each replay
// per code: 128 bf16 = [w_hi 64 | w_lo 64]  (256 B)
__device__ __nv_bfloat16 g_wb[KCODE * 128];

// ---------------------------------------------------------------------------
__device__ __forceinline__ uint32_t smem_u32(const void* p) {
    uint32_t a;
    asm("{ .reg .u64 t; cvta.to.shared.u64 t, %1; cvt.u32.u64 %0, t; }"
        : "=r"(a) : "l"(p));
    return a;
}
__device__ __forceinline__ void ldsm_x4(uint32_t& r0, uint32_t& r1,
                                        uint32_t& r2, uint32_t& r3, uint32_t addr) {
    asm volatile("ldmatrix.sync.aligned.m8n8.x4.shared.b16 {%0,%1,%2,%3}, [%4];"
                 : "=r"(r0), "=r"(r1), "=r"(r2), "=r"(r3) : "r"(addr));
}
__device__ __forceinline__ void mma_bf16(float* c, const uint32_t* a,
                                         uint32_t b0, uint32_t b1) {
    asm volatile(
        "mma.sync.aligned.m16n8k16.row.col.f32.bf16.bf16.f32 "
        "{%0,%1,%2,%3}, {%4,%5,%6,%7}, {%8,%9}, {%0,%1,%2,%3};"
        : "+f"(c[0]), "+f"(c[1]), "+f"(c[2]), "+f"(c[3])
        : "r"(a[0]), "r"(a[1]), "r"(a[2]), "r"(a[3]), "r"(b0), "r"(b1));
}
__device__ __forceinline__ void cp16(uint32_t dst, const void* src) {
    asm volatile("cp.async.cg.shared.global [%0], [%1], 16;" :: "r"(dst), "l"(src));
}
#define CP_COMMIT() asm volatile("cp.async.commit_group;" ::: "memory")
#define CP_WAIT1()  asm volatile("cp.async.wait_group 1;" ::: "memory")
#define CP_WAIT0()  asm volatile("cp.async.wait_group 0;" ::: "memory")

__device__ __forceinline__ void top2(int& m1, int& m2, int s) {
    int lo = min(m1, s);
    int hi = max(m1, s);
    m1 = lo;
    m2 = min(m2, hi);
}

// ---------------------------------------------------------------------------
// Codebook prep: one block per 128 codes, coalesced smem staging.
// Exact sequential ||w||^2 chain (reference semantics) + bf16 hi/lo split.
// Static 48KB keeps this node in the same SMEM class as k_main.
__global__ __launch_bounds__(256, 1)
void k_prep_w(const float* __restrict__ w)
{
    __shared__ __align__(16) char smem[49152];
    float* sw = (float*)smem;                    // 128 codes x 64 fp32 = 32KB
    const int tid = threadIdx.x;
    const int k0  = blockIdx.x * 128;

    // Coalesced stage: 2048 float4
    {
        const float4* src = (const float4*)(w + (size_t)k0 * DIM);
        float4* dst = (float4*)sw;
        #pragma unroll
        for (int i = 0; i < 8; ++i) dst[tid + i * 256] = src[tid + i * 256];
    }
    __syncthreads();

    // Exact sequential-chain sums (threads 0..127, one code each)
    if (tid < 128) {
        const float* r = sw + tid * DIM;
        float s = 0.0f;
        #pragma unroll
        for (int d = 0; d < DIM; ++d)
            s = __fadd_rn(s, __fmul_rn(r[d], r[d]));
        g_wsum2[k0 + tid] = s;
        g_wsC21[k0 + tid] = __fmul_rn(__fadd_rn(s, 0.25f), 2097152.0f);
    }

    // bf16 split, coalesced 2B writes
    for (int i = tid; i < 128 * DIM; i += 256) {
        int row = i >> 6, d = i & 63;
        float v = sw[i];
        __nv_bfloat16 hi = __float2bfloat16(v);
        __nv_bfloat16 lo = __float2bfloat16(__fsub_rn(v, __bfloat162float(hi)));
        g_wb[(size_t)(k0 + row) * 128 + d]      = hi;
        g_wb[(size_t)(k0 + row) * 128 + 64 + d] = lo;
    }
}

// ---------------------------------------------------------------------------
// FUSED main kernel: HMMA argmin filter + in-CTA bit-exact fallback +
// gather (z_q_st) + loss partial + last-CTA final loss reduction.
// 128 tokens/CTA, static 48KB smem, occupancy 1 (no reg cap -> no spills).
// K=192 logical split-bf16: ks0-3 z_hi.w_hi, ks4-7 z_lo.w_hi, ks8-11 z_hi.w_lo.
__global__ __launch_bounds__(256, 1)
void k_main(const float* __restrict__ z,
            const float* __restrict__ w,
            float* __restrict__ out_zq,
            float* __restrict__ out_loss,
            float* __restrict__ out_idx,
            int total_elems)
{
    __shared__ __align__(16) char smem[49152];   // A 32KB | B0 8KB | B1 8KB
    const uint32_t sbA  = smem_u32(smem);
    const uint32_t sbB0 = sbA + 32768;
    const uint32_t sbB1 = sbA + 40960;
    // post-loop aliases into the B0 region (B0 dead after tile t=30):
    int*    s_idx   = (int*)(smem + 32768);          // [128]
    int*    s_flags = (int*)(smem + 33280);          // [128]
    int*    s_nflag = (int*)(smem + 33792);
    int*    s_last  = (int*)(smem + 33808);
    double* sred    = (double*)(smem + 33824);       // [8]

    const int tid  = threadIdx.x;
    const int lane = tid & 31;
    const int warp = tid >> 5;
    const int t0   = blockIdx.x * 128;

    // Prefetch B tile 0 (32 codes x 256B)
    {
        #pragma unroll
        for (int j = 0; j < 2; ++j) {
            int ic = tid + j * 256;
            int row = ic >> 4, c = ic & 15;
            cp16(sbB0 + row * 256 + ((c ^ (row & 7)) << 4),
                 (const char*)g_wb + (size_t)row * 256 + c * 16);
        }
        CP_COMMIT();
    }

    // Stage A: 128 tokens x 256B = [z_hi 64bf16 | z_lo 64bf16], XOR-swizzled.
    {
        const float4* zsrc = (const float4*)(z + (size_t)t0 * DIM);
        #pragma unroll
        for (int it = 0; it < 8; ++it) {
            int ic = tid + it * 256;                // 2048 chunks
            int row = ic >> 4, c = ic & 15;
            int d4 = (c & 7) * 2;
            float4 v0 = zsrc[row * 16 + d4];
            float4 v1 = zsrc[row * 16 + d4 + 1];
            __nv_bfloat162 p0, p1, p2, p3;
            p0.x = __float2bfloat16(v0.x); p0.y = __float2bfloat16(v0.y);
            p1.x = __float2bfloat16(v0.z); p1.y = __float2bfloat16(v0.w);
            p2.x = __float2bfloat16(v1.x); p2.y = __float2bfloat16(v1.y);
            p3.x = __float2bfloat16(v1.z); p3.y = __float2bfloat16(v1.w);
            if (c >= 8) {
                p0.x = __float2bfloat16(__fsub_rn(v0.x, __bfloat162float(p0.x)));
                p0.y = __float2bfloat16(__fsub_rn(v0.y, __bfloat162float(p0.y)));
                p1.x = __float2bfloat16(__fsub_rn(v0.z, __bfloat162float(p1.x)));
                p1.y = __float2bfloat16(__fsub_rn(v0.w, __bfloat162float(p1.y)));
                p2.x = __float2bfloat16(__fsub_rn(v1.x, __bfloat162float(p2.x)));
                p2.y = __float2bfloat16(__fsub_rn(v1.y, __bfloat162float(p2.y)));
                p3.x = __float2bfloat16(__fsub_rn(v1.z, __bfloat162float(p3.x)));
                p3.y = __float2bfloat16(__fsub_rn(v1.w, __bfloat162float(p3.y)));
            }
            uint4 o;
            o.x = *(uint32_t*)&p0; o.y = *(uint32_t*)&p1;
            o.z = *(uint32_t*)&p2; o.w = *(uint32_t*)&p3;
            *(uint4*)(smem + row * 256 + ((c ^ (row & 7)) << 4)) = o;
        }
    }
    __syncthreads();

    // A fragments: warp covers tokens [warp*16, warp*16+16)
    uint32_t a[8][4];
    {
        const int r16   = lane & 15;
        const int chalf = lane >> 4;
        #pragma unroll
        for (int ks = 0; ks < 8; ++ks) {
            int row = warp * 16 + r16;
            int c   = ks * 2 + chalf;
            ldsm_x4(a[ks][0], a[ks][1], a[ks][2], a[ks][3],
                    sbA + row * 256 + ((c ^ (row & 7)) << 4));
        }
    }

    int m1s[2], m2s[2];
    m1s[0] = m1s[1] = 0x7FFFFFFF;
    m2s[0] = m2s[1] = 0x7FFFFFFF;

    const int brow  = (lane & 7) + ((lane >> 4) << 3);
    const int bc1   = (lane >> 3) & 1;
    const int br7   = brow & 7;
    const int klane = 2 * (lane & 3);

    #pragma unroll 1
    for (int t = 0; t < 32; ++t) {
        __syncthreads();
        if (t == 31 && tid == 0) { *s_nflag = 0; *s_last = 0; }  // B0 dead
        if (t + 1 < 32) {
            const char* src = (const char*)g_wb + (size_t)(t + 1) * 32 * 256;
            uint32_t dstb = ((t + 1) & 1) ? sbB1 : sbB0;
            #pragma unroll
            for (int j = 0; j < 2; ++j) {
                int ic = tid + j * 256;
                int row = ic >> 4, c = ic & 15;
                cp16(dstb + row * 256 + ((c ^ (row & 7)) << 4),
                     src + (size_t)row * 256 + c * 16);
            }
            CP_COMMIT();
            CP_WAIT1();
        } else {
            CP_WAIT0();
        }
        __syncthreads();

        const uint32_t bbase = ((t & 1) ? sbB1 : sbB0) + brow * 256;

        #pragma unroll
        for (int ng = 0; ng < 2; ++ng) {
            float acc[2][4];
            #pragma unroll
            for (int nf = 0; nf < 2; ++nf)
                #pragma unroll
                for (int j = 0; j < 4; ++j) acc[nf][j] = 0.0f;

            const uint32_t bgb = bbase + ng * 16 * 256;
            #pragma unroll
            for (int ks = 0; ks < 12; ++ks) {
                const int j = (ks < 8) ? (ks & 3) : ((ks & 3) + 4);
                uint32_t b0, b1, b2, b3;
                ldsm_x4(b0, b1, b2, b3, bgb + (((j * 2 + bc1) ^ br7) << 4));
                const int ka = ks & 7;       // ks 8-11 reuse z_hi frags 0-3
                mma_bf16(acc[0], a[ka], b0, b1);
                mma_bf16(acc[1], a[ka], b2, b3);
            }

            // epilogue: s = rn((b+0.25)*2^21 - 2^22*dot), pack (s<<10)|idx
            const int kb = t * 32 + ng * 16 + klane;
            #pragma unroll
            for (int nf = 0; nf < 2; ++nf) {
                const int kc = kb + nf * 8;
                const float bx = __ldg(&g_wsC21[kc]);
                const float by = __ldg(&g_wsC21[kc + 1]);
                int s0 = (__float2int_rn(__fmaf_rn(-4194304.0f, acc[nf][0], bx)) << 10) | kc;
                int s1 = (__float2int_rn(__fmaf_rn(-4194304.0f, acc[nf][1], by)) << 10) | (kc + 1);
                int s2 = (__float2int_rn(__fmaf_rn(-4194304.0f, acc[nf][2], bx)) << 10) | kc;
                int s3 = (__float2int_rn(__fmaf_rn(-4194304.0f, acc[nf][3], by)) << 10) | (kc + 1);
                top2(m1s[0], m2s[0], s0);
                top2(m1s[0], m2s[0], s1);
                top2(m1s[1], m2s[1], s2);
                top2(m1s[1], m2s[1], s3);
            }
        }
    }

    // merge across the 4 lanes sharing each row; winners into smem
    #pragma unroll
    for (int s = 0; s < 2; ++s) {
        #pragma unroll
        for (int d = 1; d <= 2; d <<= 1) {
            int om1 = __shfl_xor_sync(0xffffffffu, m1s[s], d);
            int om2 = __shfl_xor_sync(0xffffffffu, m2s[s], d);
            int hi = max(m1s[s], om1);
            m1s[s] = min(m1s[s], om1);
            m2s[s] = min(min(m2s[s], om2), hi);
        }
    }
    if ((lane & 3) == 0) {
        const int q = lane >> 2;
        #pragma unroll
        for (int s = 0; s < 2; ++s) {
            const int lt = warp * 16 + s * 8 + q;      // local token
            s_idx[lt] = m1s[s] & 1023;
            if ((m2s[s] >> 10) - (m1s[s] >> 10) <= EPS_INT) {
                int p = atomicAdd(s_nflag, 1);
                s_flags[p] = lt;
            }
        }
    }
    __syncthreads();

    // ---- In-CTA exact fallback (bit-exact reference semantics) ----
    {
        const int nflag = *s_nflag;
        #pragma unroll 1
        for (int f = warp; f < nflag; f += 8) {
            const int lt = s_flags[f];
            const size_t token = (size_t)t0 + lt;

            float zr[DIM];
            float aa = 0.0f;
            #pragma unroll
            for (int d = 0; d < DIM; ++d) {
                zr[d] = z[token * DIM + d];
                aa = __fadd_rn(aa, __fmul_rn(zr[d], zr[d]));
            }

            float best = CUDART_INF_F;
            int   bidx = 0;
            #pragma unroll 1
            for (int k0 = lane; k0 < KCODE; k0 += 128) {
                const float* w0 = w + (size_t)(k0 +  0) * DIM;
                const float* w1 = w + (size_t)(k0 + 32) * DIM;
                const float* w2 = w + (size_t)(k0 + 64) * DIM;
                const float* w3 = w + (size_t)(k0 + 96) * DIM;
                float d0 = 0.0f, d1 = 0.0f, d2 = 0.0f, d3 = 0.0f;
                #pragma unroll
                for (int d = 0; d < DIM; ++d) {
                    const float zv = zr[d];
                    d0 = __fmaf_rn(zv, w0[d], d0);
                    d1 = __fmaf_rn(zv, w1[d], d1);
                    d2 = __fmaf_rn(zv, w2[d], d2);
                    d3 = __fmaf_rn(zv, w3[d], d3);
                }
                float tt, dd;
                tt = __fadd_rn(aa, g_wsum2[k0]);
                dd = __fadd_rn(tt, -__fmul_rn(2.0f, d0));
                if (dd < best) { best = dd; bidx = k0; }
                tt = __fadd_rn(aa, g_wsum2[k0 + 32]);
                dd = __fadd_rn(tt, -__fmul_rn(2.0f, d1));
                if (dd < best) { best = dd; bidx = k0 + 32; }
                tt = __fadd_rn(aa, g_wsum2[k0 + 64]);
                dd = __fadd_rn(tt, -__fmul_rn(2.0f, d2));
                if (dd < best) { best = dd; bidx = k0 + 64; }
                tt = __fadd_rn(aa, g_wsum2[k0 + 96]);
                dd = __fadd_rn(tt, -__fmul_rn(2.0f, d3));
                if (dd < best) { best = dd; bidx = k0 + 96; }
            }
            #pragma unroll
            for (int off = 16; off > 0; off >>= 1) {
                float ov = __shfl_down_sync(0xffffffffu, best, off);
                int   oi = __shfl_down_sync(0xffffffffu, bidx, off);
                if (ov < best || (ov == best && oi < bidx)) { best = ov; bidx = oi; }
            }
            if (lane == 0) s_idx[lt] = bidx;
        }
    }
    __syncthreads();

    // ---- Fused gather: z_q_st = fl(z + fl(w[idx]-z)) + loss partial ----
    if (tid < 128) out_idx[t0 + tid] = (float)s_idx[tid];

    double accd = 0.0;
    {
        const float4* zb = (const float4*)(z + (size_t)t0 * DIM);
        #pragma unroll 1
        for (int it = 0; it < 8; ++it) {
            int ic = tid + it * 256;                // 2048 float4 units
            int row = ic >> 4, c = ic & 15;
            const int idx = s_idx[row];
            const float4 zv = zb[ic];
            const float4 wv = ((const float4*)(w + (size_t)idx * DIM))[c];

            const float dx = __fsub_rn(wv.x, zv.x);
            const float dy = __fsub_rn(wv.y, zv.y);
            const float dz = __fsub_rn(wv.z, zv.z);
            const float dw = __fsub_rn(wv.w, zv.w);

            float4 o;
            o.x = __fadd_rn(zv.x, dx);
            o.y = __fadd_rn(zv.y, dy);
            o.z = __fadd_rn(zv.z, dz);
            o.w = __fadd_rn(zv.w, dw);
            ((float4*)out_zq)[(size_t)(t0 + row) * 16 + c] = o;

            accd += (double)__fmul_rn(dx, dx);
            accd += (double)__fmul_rn(dy, dy);
            accd += (double)__fmul_rn(dz, dz);
            accd += (double)__fmul_rn(dw, dw);
        }
    }
    #pragma unroll
    for (int off = 16; off > 0; off >>= 1)
        accd += __shfl_down_sync(0xffffffffu, accd, off);
    if (lane == 0) sred[warp] = accd;
    __syncthreads();
    if (tid == 0) {
        double v = 0.0;
        #pragma unroll
        for (int i = 0; i < 8; ++i) v += sred[i];
        g_part[blockIdx.x] = v;
        __threadfence();
        int p = atomicAdd(&g_done, 1);
        *s_last = (p == (int)gridDim.x - 1) ? 1 : 0;
    }
    __syncthreads();

    // ---- Last CTA finishes: deterministic fixed-order loss reduction ----
    if (*s_last) {
        double s = 0.0;
        for (int i = tid; i < NPART; i += 256) s += g_part[i];
        #pragma unroll
        for (int off = 16; off > 0; off >>= 1)
            s += __shfl_down_sync(0xffffffffu, s, off);
        if (lane == 0) sred[warp] = s;
        __syncthreads();
        if (tid == 0) {
            double tot = 0.0;
            #pragma unroll
            for (int i = 0; i < 8; ++i) tot += sred[i];
            const float m = (float)(tot / (double)total_elems);
            out_loss[0] = __fadd_rn(m, __fmul_rn(0.25f, m));
            g_done = 0;                      // reset for next graph replay
        }
    }
}

// ---------------------------------------------------------------------------
extern "C" void kernel_launch(void* const* d_in, const int* in_sizes, int n_in,
                              void* d_out, int out_size)
{
    const float* z = (const float*)d_in[0];   // (N, 64) fp32
    const float* w = (const float*)d_in[1];   // (1024, 64) fp32

    const int ND = in_sizes[0];
    const int N  = ND / DIM;                  // 262144

    float* out      = (float*)d_out;
    float* out_zq   = out;                    // N*64 floats
    float* out_loss = out + (size_t)N * DIM;  // 1 float
    float* out_idx  = out_loss + 1;           // N floats

    // 2-node graph; both nodes in the same 48KB-static, occupancy-1 SMEM class.
    k_prep_w<<<KCODE / 128, 256>>>(w);
    k_main<<<N / 128, 256>>>(z, w, out_zq, out_loss, out_idx, ND);
}

// round 12
// speedup vs baseline: 1.0420x; 1.0420x over previous
#include <cuda_runtime.h>
#include <cuda_bf16.h>
#include <math_constants.h>
#include <cstdint>

#define DIM     64
#define KCODE   1024
#define MAXN    262144
#define EPS_INT 140          // 140 * 2^-21 ~ 6.7e-5 ambiguity window
#define NPART   8192

// ---------------------------------------------------------------------------
// Device scratch (no cudaMalloc allowed)
__device__ int       g_idx[MAXN];
__device__ float     g_wsum2[KCODE];    // exact sequential-chain ||w||^2
__device__ float     g_wsC21[KCODE];    // fl(fl(||w||^2 + 0.25) * 2^21)
__device__ int       g_flagn;
__device__ int       g_flags[MAXN];
__device__ double    g_part[NPART];
// per code: 128 bf16 = [w_hi 64 | w_lo 64]  (256 B)
__device__ __nv_bfloat16 g_wb[KCODE * 128];

// ---------------------------------------------------------------------------
__device__ __forceinline__ uint32_t smem_u32(const void* p) {
    uint32_t a;
    asm("{ .reg .u64 t; cvta.to.shared.u64 t, %1; cvt.u32.u64 %0, t; }"
        : "=r"(a) : "l"(p));
    return a;
}
__device__ __forceinline__ void ldsm_x4(uint32_t& r0, uint32_t& r1,
                                        uint32_t& r2, uint32_t& r3, uint32_t addr) {
    asm volatile("ldmatrix.sync.aligned.m8n8.x4.shared.b16 {%0,%1,%2,%3}, [%4];"
                 : "=r"(r0), "=r"(r1), "=r"(r2), "=r"(r3) : "r"(addr));
}
__device__ __forceinline__ void mma_bf16(float* c, const uint32_t* a,
                                         uint32_t b0, uint32_t b1) {
    asm volatile(
        "mma.sync.aligned.m16n8k16.row.col.f32.bf16.bf16.f32 "
        "{%0,%1,%2,%3}, {%4,%5,%6,%7}, {%8,%9}, {%0,%1,%2,%3};"
        : "+f"(c[0]), "+f"(c[1]), "+f"(c[2]), "+f"(c[3])
        : "r"(a[0]), "r"(a[1]), "r"(a[2]), "r"(a[3]), "r"(b0), "r"(b1));
}
__device__ __forceinline__ void cp16(uint32_t dst, const void* src) {
    asm volatile("cp.async.cg.shared.global [%0], [%1], 16;" :: "r"(dst), "l"(src));
}
#define CP_COMMIT() asm volatile("cp.async.commit_group;" ::: "memory")
#define CP_WAIT1()  asm volatile("cp.async.wait_group 1;" ::: "memory")
#define CP_WAIT0()  asm volatile("cp.async.wait_group 0;" ::: "memory")

__device__ __forceinline__ void top2(int& m1, int& m2, int s) {
    int lo = min(m1, s);
    int hi = max(m1, s);
    m1 = lo;
    m2 = min(m2, hi);
}

// ---------------------------------------------------------------------------
__global__ void k_zero() { g_flagn = 0; }

// ---------------------------------------------------------------------------
// Codebook prep: one block per 128 codes, coalesced smem staging.
// Exact sequential ||w||^2 chain (reference semantics) + bf16 hi/lo split.
__global__ __launch_bounds__(256, 1)
void k_prep_w(const float* __restrict__ w)
{
    __shared__ __align__(16) float sw[128 * DIM];   // 32KB
    const int tid = threadIdx.x;
    const int k0  = blockIdx.x * 128;

    // Coalesced stage: 2048 float4
    {
        const float4* src = (const float4*)(w + (size_t)k0 * DIM);
        float4* dst = (float4*)sw;
        #pragma unroll
        for (int i = 0; i < 8; ++i) dst[tid + i * 256] = src[tid + i * 256];
    }
    __syncthreads();

    // Exact sequential-chain sums (threads 0..127, one code each)
    if (tid < 128) {
        const float* r = sw + tid * DIM;
        float s = 0.0f;
        #pragma unroll
        for (int d = 0; d < DIM; ++d)
            s = __fadd_rn(s, __fmul_rn(r[d], r[d]));
        g_wsum2[k0 + tid] = s;
        g_wsC21[k0 + tid] = __fmul_rn(__fadd_rn(s, 0.25f), 2097152.0f);
    }

    // bf16 split, coalesced 2B writes
    for (int i = tid; i < 128 * DIM; i += 256) {
        int row = i >> 6, d = i & 63;
        float v = sw[i];
        __nv_bfloat16 hi = __float2bfloat16(v);
        __nv_bfloat16 lo = __float2bfloat16(__fsub_rn(v, __bfloat162float(hi)));
        g_wb[(size_t)(k0 + row) * 128 + d]      = hi;
        g_wb[(size_t)(k0 + row) * 128 + 64 + d] = lo;
    }
}

// ---------------------------------------------------------------------------
// HMMA argmin filter. UNFUSED, static 48KB smem, NO register cap.
// 128 tokens/CTA, 8 warps x M16. K=192 logical (split bf16):
//   ks0-3: z_hi.w_hi, ks4-7: z_lo.w_hi, ks8-11: z_hi.w_lo
// A: 128 x 256B = 32KB. B: 32-code tiles (8KB) double-buffered.
__global__ __launch_bounds__(256, 1)
void k_argmin_mma(const float* __restrict__ z, float* __restrict__ out_idx)
{
    __shared__ __align__(16) char smem[49152];   // A 32KB | B0 8KB | B1 8KB
    const uint32_t sbA  = smem_u32(smem);
    const uint32_t sbB0 = sbA + 32768;
    const uint32_t sbB1 = sbA + 40960;

    const int tid  = threadIdx.x;
    const int lane = tid & 31;
    const int warp = tid >> 5;
    const int t0   = blockIdx.x * 128;

    // Prefetch B tile 0 (32 codes x 256B = 512 chunks)
    {
        #pragma unroll
        for (int j = 0; j < 2; ++j) {
            int ic = tid + j * 256;
            int row = ic >> 4, c = ic & 15;
            cp16(sbB0 + row * 256 + ((c ^ (row & 7)) << 4),
                 (const char*)g_wb + (size_t)row * 256 + c * 16);
        }
        CP_COMMIT();
    }

    // Stage A: 128 tokens x 256B = [z_hi 64bf16 | z_lo 64bf16], XOR-swizzled.
    {
        const float4* zsrc = (const float4*)(z + (size_t)t0 * DIM);
        #pragma unroll
        for (int it = 0; it < 8; ++it) {
            int ic = tid + it * 256;                // 2048 chunks
            int row = ic >> 4, c = ic & 15;
            int d4 = (c & 7) * 2;
            float4 v0 = zsrc[row * 16 + d4];
            float4 v1 = zsrc[row * 16 + d4 + 1];
            __nv_bfloat162 p0, p1, p2, p3;
            p0.x = __float2bfloat16(v0.x); p0.y = __float2bfloat16(v0.y);
            p1.x = __float2bfloat16(v0.z); p1.y = __float2bfloat16(v0.w);
            p2.x = __float2bfloat16(v1.x); p2.y = __float2bfloat16(v1.y);
            p3.x = __float2bfloat16(v1.z); p3.y = __float2bfloat16(v1.w);
            if (c >= 8) {
                p0.x = __float2bfloat16(__fsub_rn(v0.x, __bfloat162float(p0.x)));
                p0.y = __float2bfloat16(__fsub_rn(v0.y, __bfloat162float(p0.y)));
                p1.x = __float2bfloat16(__fsub_rn(v0.z, __bfloat162float(p1.x)));
                p1.y = __float2bfloat16(__fsub_rn(v0.w, __bfloat162float(p1.y)));
                p2.x = __float2bfloat16(__fsub_rn(v1.x, __bfloat162float(p2.x)));
                p2.y = __float2bfloat16(__fsub_rn(v1.y, __bfloat162float(p2.y)));
                p3.x = __float2bfloat16(__fsub_rn(v1.z, __bfloat162float(p3.x)));
                p3.y = __float2bfloat16(__fsub_rn(v1.w, __bfloat162float(p3.y)));
            }
            uint4 o;
            o.x = *(uint32_t*)&p0; o.y = *(uint32_t*)&p1;
            o.z = *(uint32_t*)&p2; o.w = *(uint32_t*)&p3;
            *(uint4*)(smem + row * 256 + ((c ^ (row & 7)) << 4)) = o;
        }
    }
    __syncthreads();

    // A fragments: warp covers tokens [warp*16, warp*16+16)
    uint32_t a[8][4];
    {
        const int r16   = lane & 15;
        const int chalf = lane >> 4;
        #pragma unroll
        for (int ks = 0; ks < 8; ++ks) {
            int row = warp * 16 + r16;
            int c   = ks * 2 + chalf;
            ldsm_x4(a[ks][0], a[ks][1], a[ks][2], a[ks][3],
                    sbA + row * 256 + ((c ^ (row & 7)) << 4));
        }
    }

    int m1s[2], m2s[2];
    m1s[0] = m1s[1] = 0x7FFFFFFF;
    m2s[0] = m2s[1] = 0x7FFFFFFF;

    const int brow  = (lane & 7) + ((lane >> 4) << 3);
    const int bc1   = (lane >> 3) & 1;
    const int br7   = brow & 7;
    const int klane = 2 * (lane & 3);

    #pragma unroll 1
    for (int t = 0; t < 32; ++t) {
        __syncthreads();
        if (t + 1 < 32) {
            const char* src = (const char*)g_wb + (size_t)(t + 1) * 32 * 256;
            uint32_t dstb = ((t + 1) & 1) ? sbB1 : sbB0;
            #pragma unroll
            for (int j = 0; j < 2; ++j) {
                int ic = tid + j * 256;
                int row = ic >> 4, c = ic & 15;
                cp16(dstb + row * 256 + ((c ^ (row & 7)) << 4),
                     src + (size_t)row * 256 + c * 16);
            }
            CP_COMMIT();
            CP_WAIT1();
        } else {
            CP_WAIT0();
        }
        __syncthreads();

        const uint32_t bbase = ((t & 1) ? sbB1 : sbB0) + brow * 256;

        #pragma unroll
        for (int ng = 0; ng < 2; ++ng) {
            float acc[2][4];
            #pragma unroll
            for (int nf = 0; nf < 2; ++nf)
                #pragma unroll
                for (int j = 0; j < 4; ++j) acc[nf][j] = 0.0f;

            const uint32_t bgb = bbase + ng * 16 * 256;
            #pragma unroll
            for (int ks = 0; ks < 12; ++ks) {
                const int j = (ks < 8) ? (ks & 3) : ((ks & 3) + 4);
                uint32_t b0, b1, b2, b3;
                ldsm_x4(b0, b1, b2, b3, bgb + (((j * 2 + bc1) ^ br7) << 4));
                const int ka = ks & 7;       // ks 8-11 reuse z_hi frags 0-3
                mma_bf16(acc[0], a[ka], b0, b1);
                mma_bf16(acc[1], a[ka], b2, b3);
            }

            // epilogue: s = rn((b+0.25)*2^21 - 2^22*dot), pack (s<<10)|idx
            const int kb = t * 32 + ng * 16 + klane;
            #pragma unroll
            for (int nf = 0; nf < 2; ++nf) {
                const int kc = kb + nf * 8;
                const float bx = __ldg(&g_wsC21[kc]);
                const float by = __ldg(&g_wsC21[kc + 1]);
                int s0 = (__float2int_rn(__fmaf_rn(-4194304.0f, acc[nf][0], bx)) << 10) | kc;
                int s1 = (__float2int_rn(__fmaf_rn(-4194304.0f, acc[nf][1], by)) << 10) | (kc + 1);
                int s2 = (__float2int_rn(__fmaf_rn(-4194304.0f, acc[nf][2], bx)) << 10) | kc;
                int s3 = (__float2int_rn(__fmaf_rn(-4194304.0f, acc[nf][3], by)) << 10) | (kc + 1);
                top2(m1s[0], m2s[0], s0);
                top2(m1s[0], m2s[0], s1);
                top2(m1s[1], m2s[1], s2);
                top2(m1s[1], m2s[1], s3);
            }
        }
    }

    // merge across the 4 lanes sharing each row
    #pragma unroll
    for (int s = 0; s < 2; ++s) {
        #pragma unroll
        for (int d = 1; d <= 2; d <<= 1) {
            int om1 = __shfl_xor_sync(0xffffffffu, m1s[s], d);
            int om2 = __shfl_xor_sync(0xffffffffu, m2s[s], d);
            int hi = max(m1s[s], om1);
            m1s[s] = min(m1s[s], om1);
            m2s[s] = min(min(m2s[s], om2), hi);
        }
    }
    if ((lane & 3) == 0) {
        const int q = lane >> 2;
        #pragma unroll
        for (int s = 0; s < 2; ++s) {
            const int token = t0 + warp * 16 + s * 8 + q;
            const int k1 = m1s[s] & 1023;
            g_idx[token]   = k1;
            out_idx[token] = (float)k1;
            if ((m2s[s] >> 10) - (m1s[s] >> 10) <= EPS_INT) {
                int p = atomicAdd(&g_flagn, 1);
                g_flags[p] = token;
            }
        }
    }
}

// ---------------------------------------------------------------------------
// Exact fallback: bit-exact reference semantics for flagged tokens.
__global__ __launch_bounds__(256)
void k_exact(const float* __restrict__ z,
             const float* __restrict__ w,
             float* __restrict__ out_idx)
{
    const int lane = threadIdx.x & 31;
    const int gw   = (blockIdx.x * blockDim.x + threadIdx.x) >> 5;
    const int nw   = (gridDim.x * blockDim.x) >> 5;
    const int nflag = g_flagn;

    for (int i = gw; i < nflag; i += nw) {
        const size_t token = (size_t)g_flags[i];

        float zr[DIM];
        float a = 0.0f;
        #pragma unroll
        for (int d = 0; d < DIM; ++d) {
            zr[d] = z[token * DIM + d];
            a = __fadd_rn(a, __fmul_rn(zr[d], zr[d]));
        }

        float best = CUDART_INF_F;
        int   bidx = 0;

        for (int k0 = lane; k0 < KCODE; k0 += 128) {
            const float* w0 = w + (size_t)(k0 +  0) * DIM;
            const float* w1 = w + (size_t)(k0 + 32) * DIM;
            const float* w2 = w + (size_t)(k0 + 64) * DIM;
            const float* w3 = w + (size_t)(k0 + 96) * DIM;
            float d0 = 0.0f, d1 = 0.0f, d2 = 0.0f, d3 = 0.0f;
            #pragma unroll
            for (int d = 0; d < DIM; ++d) {
                const float zv = zr[d];
                d0 = __fmaf_rn(zv, w0[d], d0);
                d1 = __fmaf_rn(zv, w1[d], d1);
                d2 = __fmaf_rn(zv, w2[d], d2);
                d3 = __fmaf_rn(zv, w3[d], d3);
            }
            float tt, dd;
            tt = __fadd_rn(a, g_wsum2[k0]);
            dd = __fadd_rn(tt, -__fmul_rn(2.0f, d0));
            if (dd < best) { best = dd; bidx = k0; }
            tt = __fadd_rn(a, g_wsum2[k0 + 32]);
            dd = __fadd_rn(tt, -__fmul_rn(2.0f, d1));
            if (dd < best) { best = dd; bidx = k0 + 32; }
            tt = __fadd_rn(a, g_wsum2[k0 + 64]);
            dd = __fadd_rn(tt, -__fmul_rn(2.0f, d2));
            if (dd < best) { best = dd; bidx = k0 + 64; }
            tt = __fadd_rn(a, g_wsum2[k0 + 96]);
            dd = __fadd_rn(tt, -__fmul_rn(2.0f, d3));
            if (dd < best) { best = dd; bidx = k0 + 96; }
        }

        #pragma unroll
        for (int off = 16; off > 0; off >>= 1) {
            float ov = __shfl_down_sync(0xffffffffu, best, off);
            int   oi = __shfl_down_sync(0xffffffffu, bidx, off);
            if (ov < best || (ov == best && oi < bidx)) { best = ov; bidx = oi; }
        }
        if (lane == 0) {
            g_idx[token]   = bidx;
            out_idx[token] = (float)bidx;
        }
    }
}

// ---------------------------------------------------------------------------
// Gather z_q_st = fl(z + fl(w[idx] - z)); per-block double partial (no atomic).
__global__ __launch_bounds__(512)
void k_gather(const float* __restrict__ z,
              const float* __restrict__ w,
              float* __restrict__ out_zq)
{
    __shared__ double sred[16];
    const int tid = threadIdx.x;
    const size_t token = (size_t)blockIdx.x * 32 + (tid >> 4);
    const int c = tid & 15;

    const int idx = g_idx[token];
    const float4 wv = ((const float4*)(w + (size_t)idx * DIM))[c];
    const float4 zv = ((const float4*)(z + token * DIM))[c];

    const float dx = __fsub_rn(wv.x, zv.x);
    const float dy = __fsub_rn(wv.y, zv.y);
    const float dz = __fsub_rn(wv.z, zv.z);
    const float dw = __fsub_rn(wv.w, zv.w);

    float4 o;
    o.x = __fadd_rn(zv.x, dx);
    o.y = __fadd_rn(zv.y, dy);
    o.z = __fadd_rn(zv.z, dz);
    o.w = __fadd_rn(zv.w, dw);
    ((float4*)out_zq)[token * (DIM / 4) + c] = o;

    double s = (double)__fmul_rn(dx, dx);
    s += (double)__fmul_rn(dy, dy);
    s += (double)__fmul_rn(dz, dz);
    s += (double)__fmul_rn(dw, dw);

    #pragma unroll
    for (int off = 16; off > 0; off >>= 1)
        s += __shfl_down_sync(0xffffffffu, s, off);

    const int wrp = tid >> 5;
    if ((tid & 31) == 0) sred[wrp] = s;
    __syncthreads();

    if (wrp == 0) {
        double v = (tid < 16) ? sred[tid] : 0.0;
        #pragma unroll
        for (int off = 8; off > 0; off >>= 1)
            v += __shfl_down_sync(0xffffffffu, v, off);
        if (tid == 0) g_part[blockIdx.x] = v;
    }
}

// ---------------------------------------------------------------------------
__global__ __launch_bounds__(256)
void k_final(float* __restrict__ out_loss, int total_elems)
{
    __shared__ double sm[8];
    const int tid = threadIdx.x;
    double s = 0.0;
    for (int i = tid; i < NPART; i += 256) s += g_part[i];
    #pragma unroll
    for (int off = 16; off > 0; off >>= 1)
        s += __shfl_down_sync(0xffffffffu, s, off);
    if ((tid & 31) == 0) sm[tid >> 5] = s;
    __syncthreads();
    if (tid == 0) {
        double tot = 0.0;
        #pragma unroll
        for (int i = 0; i < 8; ++i) tot += sm[i];
        const float m = (float)(tot / (double)total_elems);
        out_loss[0] = __fadd_rn(m, __fmul_rn(0.25f, m));
    }
}

// ---------------------------------------------------------------------------
extern "C" void kernel_launch(void* const* d_in, const int* in_sizes, int n_in,
                              void* d_out, int out_size)
{
    const float* z = (const float*)d_in[0];   // (N, 64) fp32
    const float* w = (const float*)d_in[1];   // (1024, 64) fp32

    const int ND = in_sizes[0];
    const int N  = ND / DIM;                  // 262144

    float* out      = (float*)d_out;
    float* out_zq   = out;                    // N*64 floats
    float* out_loss = out + (size_t)N * DIM;  // 1 float
    float* out_idx  = out_loss + 1;           // N floats

    // All static smem <= 48KB, no attribute calls, no reg caps (no spills).
    k_zero<<<1, 1>>>();
    k_prep_w<<<KCODE / 128, 256>>>(w);
    k_argmin_mma<<<N / 128, 256>>>(z, out_idx);
    k_exact<<<256, 256>>>(z, w, out_idx);
    k_gather<<<N / 32, 512>>>(z, w, out_zq);
    k_final<<<1, 256>>>(out_loss, ND);
}